// round 5
// baseline (speedup 1.0000x reference)
#include <cuda_runtime.h>
#include <cuda_bf16.h>
#include <cstdint>
#include <cstddef>

// Problem constants
#define BB   4
#define TT   2048
#define DM   1024
#define DI   2048
#define DX   4096
#define MROWS (BB*TT)   // 8192

// GEMM tiling
#define BKC   32                 // k elems per chunk
#define PITCH 40                 // bf16 elems per smem row (32 + 8 pad)
#define TILE_ELEMS (128*PITCH)   // 5120 bf16
#define TILE_BYTES (TILE_ELEMS*2)
#define GEMM_SMEM (8*TILE_BYTES + 1024)

// ---------------- scratch ----------------------------------------------------
__device__ float g_xz [(size_t)MROWS * DX];
__device__ float g_lam[(size_t)MROWS * DI];
__device__ float g_v  [(size_t)MROWS * DI];
__device__ float g_g  [(size_t)MROWS * DI];
__device__ float g_sv2[(size_t)MROWS];       // 2/(v.v)
__device__ float g_fcol[DI];                 // -8*softplus(omega)

// ---------------- helpers ------------------------------------------------------
__device__ __forceinline__ uint32_t smem_u32(const void* p) {
    uint32_t a;
    asm("{ .reg .u64 t; cvta.to.shared.u64 t, %1; cvt.u32.u64 %0, t; }" : "=r"(a) : "l"(p));
    return a;
}
__device__ __forceinline__ void mma_bf16(float* c, const uint32_t* a, const uint32_t* b) {
    asm volatile(
        "mma.sync.aligned.m16n8k16.row.col.f32.bf16.bf16.f32 "
        "{%0,%1,%2,%3}, {%4,%5,%6,%7}, {%8,%9}, {%0,%1,%2,%3};"
        : "+f"(c[0]), "+f"(c[1]), "+f"(c[2]), "+f"(c[3])
        : "r"(a[0]), "r"(a[1]), "r"(a[2]), "r"(a[3]), "r"(b[0]), "r"(b[1]));
}
#define LDSM_X4(r, addr) \
    asm volatile("ldmatrix.sync.aligned.m8n8.x4.shared.b16 {%0,%1,%2,%3}, [%4];" \
        : "=r"((r)[0]), "=r"((r)[1]), "=r"((r)[2]), "=r"((r)[3]) : "r"(addr))

// fp32x4 -> hi/lo bf16 split, stored as uint2 (4 bf16) each
__device__ __forceinline__ void store_split(__nv_bfloat16* hi, __nv_bfloat16* lo,
                                            int off, float4 f) {
    __nv_bfloat162 h0 = __float22bfloat162_rn(make_float2(f.x, f.y));
    __nv_bfloat162 h1 = __float22bfloat162_rn(make_float2(f.z, f.w));
    float2 g0 = __bfloat1622float2(h0);
    float2 g1 = __bfloat1622float2(h1);
    __nv_bfloat162 l0 = __float22bfloat162_rn(make_float2(f.x - g0.x, f.y - g0.y));
    __nv_bfloat162 l1 = __float22bfloat162_rn(make_float2(f.z - g1.x, f.w - g1.y));
    uint2 hv, lv;
    hv.x = *(uint32_t*)&h0; hv.y = *(uint32_t*)&h1;
    lv.x = *(uint32_t*)&l0; lv.y = *(uint32_t*)&l1;
    *(uint2*)(hi + off) = hv;
    *(uint2*)(lo + off) = lv;
}

// ---------------- fcol precompute -----------------------------------------------
__global__ void fcol_kernel(const float* __restrict__ omega, float* __restrict__ fcol) {
    int i = blockIdx.x * 256 + threadIdx.x;
    if (i < DI) fcol[i] = -8.0f * log1pf(__expf(omega[i]));
}

// ---------------- NT GEMM: C[M,N] = A[M,K] * B[N,K]^T ---------------------------
// mode 0: C = acc + bias
// mode 1: C = exp(fcol[col] * sigmoid(acc + bias))
// mode 2: C = silu(acc) on columns >= DI (z half), plain otherwise
__global__ __launch_bounds__(256, 1) void gemm_tc(
    const float* __restrict__ A, int lda,
    const float* __restrict__ B, int ldb,
    float* __restrict__ C, int ldc, int K,
    const float* __restrict__ bias,
    const float* __restrict__ fcolg, int mode)
{
    extern __shared__ char smraw[];
    __nv_bfloat16* sA = (__nv_bfloat16*)smraw;                      // [stage][hi/lo]
    __nv_bfloat16* sB = (__nv_bfloat16*)(smraw + 4 * TILE_BYTES);
    float* bias_s = (float*)(smraw + 8 * TILE_BYTES);
    float* fcol_s = bias_s + 128;

    const int tid = threadIdx.x;
    const int wid = tid >> 5, lane = tid & 31;
    const int g = lane >> 2, tq = lane & 3;
    const int wm = wid >> 2, wn = wid & 3;       // warp grid 2 x 4, tiles 64 x 32
    const int rowBase = blockIdx.y * 128;
    const int colBase = blockIdx.x * 128;
    const bool dosilu = (mode == 2) && (colBase >= DI);

    if (tid < 128) {
        int c = colBase + tid;
        bias_s[tid] = bias ? bias[c] : 0.f;
        fcol_s[tid] = (mode == 1) ? fcolg[c] : 0.f;
    }

    const int nc = K / BKC;
    float4 ra[4], rb[4];

    // prologue: load chunk 0
    #pragma unroll
    for (int i = 0; i < 4; i++) {
        const int idx = i * 256 + tid, row = idx >> 3, kq = idx & 7;
        ra[i] = *(const float4*)(A + (size_t)(rowBase + row) * lda + kq * 4);
        rb[i] = *(const float4*)(B + (size_t)(colBase + row) * ldb + kq * 4);
    }
    #pragma unroll
    for (int i = 0; i < 4; i++) {
        const int idx = i * 256 + tid, row = idx >> 3, kq = idx & 7;
        const int off = row * PITCH + kq * 4;
        store_split(sA, sA + TILE_ELEMS, off, ra[i]);
        store_split(sB, sB + TILE_ELEMS, off, rb[i]);
    }
    __syncthreads();

    float acc[4][4][4];
    #pragma unroll
    for (int mt = 0; mt < 4; mt++)
        #pragma unroll
        for (int nt = 0; nt < 4; nt++)
            #pragma unroll
            for (int j = 0; j < 4; j++) acc[mt][nt][j] = 0.f;

    const uint32_t smem_u = smem_u32(smraw);
    const int lr = lane & 15, lcq = (lane >> 4) << 3;

    for (int c = 0; c < nc; c++) {
        const int s = c & 1;
        if (c + 1 < nc) {
            const int kb = (c + 1) * BKC;
            #pragma unroll
            for (int i = 0; i < 4; i++) {
                const int idx = i * 256 + tid, row = idx >> 3, kq = idx & 7;
                ra[i] = *(const float4*)(A + (size_t)(rowBase + row) * lda + kb + kq * 4);
                rb[i] = *(const float4*)(B + (size_t)(colBase + row) * ldb + kb + kq * 4);
            }
        }

        const uint32_t uAh = smem_u + (uint32_t)(s * 2 + 0) * TILE_BYTES;
        const uint32_t uAl = uAh + TILE_BYTES;
        const uint32_t uBh = smem_u + (uint32_t)(4 + s * 2) * TILE_BYTES;
        const uint32_t uBl = uBh + TILE_BYTES;

        #pragma unroll
        for (int kk = 0; kk < 2; kk++) {
            const int kc = kk * 16;
            uint32_t ah[4][4], al[4][4], bh[2][4], bl[2][4];
            #pragma unroll
            for (int mt = 0; mt < 4; mt++) {
                const uint32_t off = (uint32_t)(((wm * 64 + mt * 16 + lr) * PITCH + kc + lcq) * 2);
                LDSM_X4(ah[mt], uAh + off);
                LDSM_X4(al[mt], uAl + off);
            }
            #pragma unroll
            for (int p = 0; p < 2; p++) {
                const uint32_t off = (uint32_t)(((wn * 32 + p * 16 + lr) * PITCH + kc + lcq) * 2);
                LDSM_X4(bh[p], uBh + off);
                LDSM_X4(bl[p], uBl + off);
            }
            // b-pair views: nt -> {x4 reg0/1 (k0-7), reg2/3 (k8-15)}
            uint32_t bH[4][2] = {{bh[0][0], bh[0][2]}, {bh[0][1], bh[0][3]},
                                 {bh[1][0], bh[1][2]}, {bh[1][1], bh[1][3]}};
            uint32_t bL[4][2] = {{bl[0][0], bl[0][2]}, {bl[0][1], bl[0][3]},
                                 {bl[1][0], bl[1][2]}, {bl[1][1], bl[1][3]}};
            #pragma unroll
            for (int mt = 0; mt < 4; mt++)
                #pragma unroll
                for (int nt = 0; nt < 4; nt++)
                    mma_bf16(acc[mt][nt], ah[mt], bH[nt]);
            #pragma unroll
            for (int mt = 0; mt < 4; mt++)
                #pragma unroll
                for (int nt = 0; nt < 4; nt++)
                    mma_bf16(acc[mt][nt], ah[mt], bL[nt]);
            #pragma unroll
            for (int mt = 0; mt < 4; mt++)
                #pragma unroll
                for (int nt = 0; nt < 4; nt++)
                    mma_bf16(acc[mt][nt], al[mt], bH[nt]);
        }

        if (c + 1 < nc) {
            const int s1 = s ^ 1;
            __nv_bfloat16* dAh = sA + (s1 * 2 + 0) * TILE_ELEMS;
            __nv_bfloat16* dAl = sA + (s1 * 2 + 1) * TILE_ELEMS;
            __nv_bfloat16* dBh = sB + (s1 * 2 + 0) * TILE_ELEMS;
            __nv_bfloat16* dBl = sB + (s1 * 2 + 1) * TILE_ELEMS;
            #pragma unroll
            for (int i = 0; i < 4; i++) {
                const int idx = i * 256 + tid, row = idx >> 3, kq = idx & 7;
                const int off = row * PITCH + kq * 4;
                store_split(dAh, dAl, off, ra[i]);
                store_split(dBh, dBl, off, rb[i]);
            }
        }
        __syncthreads();
    }

    // epilogue
    #pragma unroll
    for (int mt = 0; mt < 4; mt++) {
        const int r0 = rowBase + wm * 64 + mt * 16 + g;
        #pragma unroll
        for (int nt = 0; nt < 4; nt++) {
            const int col = wn * 32 + nt * 8 + tq * 2;
            float v0 = acc[mt][nt][0] + bias_s[col];
            float v1 = acc[mt][nt][1] + bias_s[col + 1];
            float v2 = acc[mt][nt][2] + bias_s[col];
            float v3 = acc[mt][nt][3] + bias_s[col + 1];
            if (mode == 1) {
                const float f0 = fcol_s[col], f1 = fcol_s[col + 1];
                v0 = __expf(f0 * __frcp_rn(1.0f + __expf(-v0)));
                v1 = __expf(f1 * __frcp_rn(1.0f + __expf(-v1)));
                v2 = __expf(f0 * __frcp_rn(1.0f + __expf(-v2)));
                v3 = __expf(f1 * __frcp_rn(1.0f + __expf(-v3)));
            } else if (dosilu) {
                v0 = v0 * __frcp_rn(1.0f + __expf(-v0));
                v1 = v1 * __frcp_rn(1.0f + __expf(-v1));
                v2 = v2 * __frcp_rn(1.0f + __expf(-v2));
                v3 = v3 * __frcp_rn(1.0f + __expf(-v3));
            }
            float* p0 = C + (size_t)r0 * ldc + colBase + col;
            float* p1 = C + (size_t)(r0 + 8) * ldc + colBase + col;
            *(float2*)p0 = make_float2(v0, v1);
            *(float2*)p1 = make_float2(v2, v3);
        }
    }
}

// ---------------- 2/(v.v) per row ------------------------------------------------
__global__ __launch_bounds__(256) void vv_kernel(const float* __restrict__ v,
                                                 float* __restrict__ sv2)
{
    __shared__ float sm[8];
    const int row = blockIdx.x, tid = threadIdx.x;
    const float4* vr = (const float4*)(v + (size_t)row * DI);
    float s = 0.f;
    #pragma unroll
    for (int i = 0; i < 2; i++) {
        float4 a = vr[tid + i * 256];
        s += a.x * a.x + a.y * a.y + a.z * a.z + a.w * a.w;
    }
    #pragma unroll
    for (int o = 16; o; o >>= 1) s += __shfl_xor_sync(0xffffffffu, s, o);
    if ((tid & 31) == 0) sm[tid >> 5] = s;
    __syncthreads();
    if (tid == 0) {
        float t = 0.f;
        #pragma unroll
        for (int w = 0; w < 8; w++) t += sm[w];
        sv2[row] = 2.0f / t;
    }
}

// ---------------- sequential scan: one CTA per batch ------------------------------
// z-half of xz holds silu(z) already; sv2 = 2/(v.v)
__global__ __launch_bounds__(1024) void scan_kernel(
    const float* __restrict__ xz, const float* __restrict__ lam,
    const float* __restrict__ v, const float* __restrict__ sv2,
    float* __restrict__ g)
{
    __shared__ float red[64];
    const int b = blockIdx.x;
    const int tid = threadIdx.x;
    const int lane = tid & 31, wrp = tid >> 5;
    const int n2 = tid * 2;

    const float* xib  = xz  + (size_t)b * TT * DX;
    const float* szb  = xib + DI;                 // silu(z)
    const float* lamb = lam + (size_t)b * TT * DI;
    const float* vb   = v   + (size_t)b * TT * DI;
    const float* svb  = sv2 + (size_t)b * TT;
    float*       gb   = g   + (size_t)b * TT * DI;

    float2 h = *(const float2*)(xib + n2);
    {
        float2 s0 = *(const float2*)(szb + n2);
        *(float2*)(gb + n2) = make_float2(s0.x * h.x, s0.y * h.y);
    }

    for (int t = 1; t < TT; t++) {
        const size_t o2 = (size_t)t * DI + n2;
        const size_t o4 = (size_t)t * DX + n2;
        const float2 vt = *(const float2*)(vb + o2);
        float p = vt.x * h.x + vt.y * h.y;

        // prefetch step-t operands (independent of reduction)
        const float2 lt = *(const float2*)(lamb + o2);
        const float2 xt = *(const float2*)(xib + o4);
        const float2 st = *(const float2*)(szb + o4);
        const float sv  = svb[t];

        #pragma unroll
        for (int o = 16; o; o >>= 1) p += __shfl_xor_sync(0xffffffffu, p, o);
        const int rbase = (t & 1) << 5;
        if (lane == 0) red[rbase + wrp] = p;
        __syncthreads();
        float q = red[rbase + lane];
        #pragma unroll
        for (int o = 16; o; o >>= 1) q += __shfl_xor_sync(0xffffffffu, q, o);

        const float s2 = q * sv;
        h.x = lt.x * (h.x - s2 * vt.x) + (1.0f - lt.x) * xt.x;
        h.y = lt.y * (h.y - s2 * vt.y) + (1.0f - lt.y) * xt.y;

        *(float2*)(gb + o2) = make_float2(st.x * h.x, st.y * h.y);
    }
}

// ---------------- launcher ----------------------------------------------------------
extern "C" void kernel_launch(void* const* d_in, const int* in_sizes, int n_in,
                              void* d_out, int out_size)
{
    const float* x     = (const float*)d_in[0];
    const float* omega = (const float*)d_in[1];
    const float* Win   = (const float*)d_in[2];
    const float* Wl    = (const float*)d_in[3];
    const float* bl    = (const float*)d_in[4];
    const float* Wv    = (const float*)d_in[5];
    const float* bv    = (const float*)d_in[6];
    const float* Wout  = (const float*)d_in[7];
    float* out = (float*)d_out;

    float* xz;   cudaGetSymbolAddress((void**)&xz,   g_xz);
    float* lam;  cudaGetSymbolAddress((void**)&lam,  g_lam);
    float* v;    cudaGetSymbolAddress((void**)&v,    g_v);
    float* gg;   cudaGetSymbolAddress((void**)&gg,   g_g);
    float* sv2;  cudaGetSymbolAddress((void**)&sv2,  g_sv2);
    float* fcol; cudaGetSymbolAddress((void**)&fcol, g_fcol);

    static int smem_set = 0;
    if (!smem_set) {
        cudaFuncSetAttribute(gemm_tc, cudaFuncAttributeMaxDynamicSharedMemorySize, GEMM_SMEM);
        smem_set = 1;
    }

    // 0) fcol = -8*softplus(omega)      (also shifts ncu capture idx3 -> GEMM 3)
    fcol_kernel<<<DI / 256, 256>>>(omega, fcol);

    // 1) xz = x @ Win^T ; silu applied to z-half columns
    gemm_tc<<<dim3(DX / 128, MROWS / 128), 256, GEMM_SMEM>>>(
        x, DM, Win, DM, xz, DX, DM, nullptr, nullptr, 2);

    // 2) lam = exp(fcol * sigmoid(xi @ Wl^T + bl))
    gemm_tc<<<dim3(DI / 128, MROWS / 128), 256, GEMM_SMEM>>>(
        xz, DX, Wl, DI, lam, DI, DI, bl, fcol, 1);

    // 3) v = xi @ Wv^T + bv
    gemm_tc<<<dim3(DI / 128, MROWS / 128), 256, GEMM_SMEM>>>(
        xz, DX, Wv, DI, v, DI, DI, bv, nullptr, 0);

    // 4) sv2 = 2/(v.v)
    vv_kernel<<<MROWS, 256>>>(v, sv2);

    // 5) scan
    scan_kernel<<<BB, 1024>>>(xz, lam, v, sv2, gg);

    // 6) out = g @ Wout^T
    gemm_tc<<<dim3(DM / 128, MROWS / 128), 256, GEMM_SMEM>>>(
        gg, DI, Wout, DI, out, DM, DI, nullptr, nullptr, 0);
}

// round 6
// speedup vs baseline: 1.2680x; 1.2680x over previous
#include <cuda_runtime.h>
#include <cuda_bf16.h>
#include <cstdint>
#include <cstddef>

// Problem constants
#define BB   4
#define TT   2048
#define DM   1024
#define DI   2048
#define DX   4096
#define MROWS (BB*TT)   // 8192

// GEMM tiling
#define BKC   32
#define PITCH 40                       // bf16 per smem row (32 + 8 pad)
#define TILE_BYTES (128*PITCH*2)       // 10240
#define STAGE_BYTES (4*TILE_BYTES)     // Ah,Al,Bh,Bl
#define GEMM_SMEM (3*STAGE_BYTES + 1024)

// Scan config
#define SCP  5                          // prefetch ring depth
#define SCT  512                        // threads
#define SCAN_SMEM ((SCP*4*DI + DI + 32)*4)   // ring + sv + partials

// ---------------- scratch ----------------------------------------------------
__device__ __nv_bfloat16 g_xh [(size_t)MROWS * DM],  g_xl [(size_t)MROWS * DM];
__device__ __nv_bfloat16 g_winh[(size_t)DX * DM],    g_winl[(size_t)DX * DM];
__device__ __nv_bfloat16 g_wlh[(size_t)DI * DI],     g_wll[(size_t)DI * DI];
__device__ __nv_bfloat16 g_wvh[(size_t)DI * DI],     g_wvl[(size_t)DI * DI];
__device__ __nv_bfloat16 g_woh[(size_t)DM * DI],     g_wol[(size_t)DM * DI];
__device__ float         g_xi [(size_t)MROWS * DI];
__device__ __nv_bfloat16 g_xih[(size_t)MROWS * DI],  g_xil[(size_t)MROWS * DI];
__device__ float         g_sz [(size_t)MROWS * DI];
__device__ float         g_lam[(size_t)MROWS * DI];
__device__ float         g_v  [(size_t)MROWS * DI];
__device__ __nv_bfloat16 g_gh [(size_t)MROWS * DI],  g_gl [(size_t)MROWS * DI];
__device__ float         g_sv2[(size_t)MROWS];
__device__ float         g_fcolA[DI];

// ---------------- helpers ------------------------------------------------------
__device__ __forceinline__ uint32_t smem_u32(const void* p) {
    uint32_t a;
    asm("{ .reg .u64 t; cvta.to.shared.u64 t, %1; cvt.u32.u64 %0, t; }" : "=r"(a) : "l"(p));
    return a;
}
__device__ __forceinline__ void cp16(uint32_t dst, const void* src) {
    asm volatile("cp.async.cg.shared.global [%0], [%1], 16;" :: "r"(dst), "l"(src));
}
#define CP_COMMIT() asm volatile("cp.async.commit_group;" ::: "memory")
#define CP_WAIT(n)  asm volatile("cp.async.wait_group %0;" :: "n"(n) : "memory")

__device__ __forceinline__ void mma_bf16(float* c, const uint32_t* a, const uint32_t* b) {
    asm volatile(
        "mma.sync.aligned.m16n8k16.row.col.f32.bf16.bf16.f32 "
        "{%0,%1,%2,%3}, {%4,%5,%6,%7}, {%8,%9}, {%0,%1,%2,%3};"
        : "+f"(c[0]), "+f"(c[1]), "+f"(c[2]), "+f"(c[3])
        : "r"(a[0]), "r"(a[1]), "r"(a[2]), "r"(a[3]), "r"(b[0]), "r"(b[1]));
}
#define LDSM_X4(r, addr) \
    asm volatile("ldmatrix.sync.aligned.m8n8.x4.shared.b16 {%0,%1,%2,%3}, [%4];" \
        : "=r"((r)[0]), "=r"((r)[1]), "=r"((r)[2]), "=r"((r)[3]) : "r"(addr))

__device__ __forceinline__ void split2(float a, float b, uint32_t& hv, uint32_t& lv) {
    __nv_bfloat162 h = __float22bfloat162_rn(make_float2(a, b));
    float2 hf = __bfloat1622float2(h);
    __nv_bfloat162 l = __float22bfloat162_rn(make_float2(a - hf.x, b - hf.y));
    hv = *(uint32_t*)&h; lv = *(uint32_t*)&l;
}

// ---------------- pre-split: fp32 -> hi/lo bf16 ---------------------------------
__global__ __launch_bounds__(256) void split_kernel(
    const float* __restrict__ src, __nv_bfloat16* __restrict__ hi,
    __nv_bfloat16* __restrict__ lo, int n)
{
    int i = (blockIdx.x * 256 + threadIdx.x) * 4;
    if (i >= n) return;
    float4 f = *(const float4*)(src + i);
    uint32_t h0, l0, h1, l1;
    split2(f.x, f.y, h0, l0);
    split2(f.z, f.w, h1, l1);
    uint2 hv = make_uint2(h0, h1), lv = make_uint2(l0, l1);
    *(uint2*)(hi + i) = hv;
    *(uint2*)(lo + i) = lv;
}

__global__ void fcol_kernel(const float* __restrict__ omega, float* __restrict__ fcol) {
    int i = blockIdx.x * 256 + threadIdx.x;
    if (i < DI) fcol[i] = -8.0f * log1pf(__expf(omega[i]));
}

// ---------------- NT GEMM on pre-split operands ---------------------------------
// C[M,N] = (Ah+Al)[M,K] * (Bh+Bl)[N,K]^T  via 3-term bf16 mma
// mode 0: C0 = acc + bias
// mode 1: C0 = exp(fcol[col]*sigmoid(acc+bias))
// mode 2: col<DI: C0=acc (fp32) AND split->Chi/Clo ; col>=DI: Csz = silu(acc)
__global__ __launch_bounds__(256, 1) void gemm_ps(
    const __nv_bfloat16* __restrict__ Ahg, const __nv_bfloat16* __restrict__ Alg, int lda,
    const __nv_bfloat16* __restrict__ Bhg, const __nv_bfloat16* __restrict__ Blg, int ldb,
    int K,
    float* __restrict__ C0, int ldc,
    const float* __restrict__ bias, const float* __restrict__ fcolg,
    __nv_bfloat16* __restrict__ Chi, __nv_bfloat16* __restrict__ Clo,
    float* __restrict__ Csz, int mode)
{
    extern __shared__ char smraw[];
    const uint32_t smem_u = smem_u32(smraw);
    float* bias_s = (float*)(smraw + 3 * STAGE_BYTES);
    float* fcol_s = bias_s + 128;

    const int tid = threadIdx.x;
    const int wid = tid >> 5, lane = tid & 31;
    const int g = lane >> 2, tq = lane & 3;
    const int wm = wid >> 2, wn = wid & 3;
    const int rowBase = blockIdx.y * 128;
    const int colBase = blockIdx.x * 128;

    if (tid < 128) {
        int c = colBase + tid;
        bias_s[tid] = bias ? bias[c] : 0.f;
        fcol_s[tid] = (mode == 1) ? fcolg[c] : 0.f;
    }

    const int nc = K / BKC;
    const int u0 = tid, u1 = tid + 256;   // 512 16B-units per tile

    // fill chunk c into stage s
    auto fill = [&](int c, int s) {
        const uint32_t sb = smem_u + (uint32_t)s * STAGE_BYTES;
        #pragma unroll
        for (int i = 0; i < 2; i++) {
            const int unit = i ? u1 : u0;
            const int row = unit >> 2, seg = unit & 3;
            const uint32_t so = (uint32_t)(row * PITCH + seg * 8) * 2;
            const size_t ga = (size_t)(rowBase + row) * lda + c * BKC + seg * 8;
            const size_t gb = (size_t)(colBase + row) * ldb + c * BKC + seg * 8;
            cp16(sb + 0 * TILE_BYTES + so, Ahg + ga);
            cp16(sb + 1 * TILE_BYTES + so, Alg + ga);
            cp16(sb + 2 * TILE_BYTES + so, Bhg + gb);
            cp16(sb + 3 * TILE_BYTES + so, Blg + gb);
        }
        CP_COMMIT();
    };

    fill(0, 0);
    fill(1, 1);
    CP_WAIT(1);

    float acc[4][4][4];
    #pragma unroll
    for (int mt = 0; mt < 4; mt++)
        #pragma unroll
        for (int nt = 0; nt < 4; nt++)
            #pragma unroll
            for (int j = 0; j < 4; j++) acc[mt][nt][j] = 0.f;

    const int lr = lane & 15, lcq = (lane >> 4) << 3;

    for (int c = 0; c < nc; c++) {
        __syncthreads();
        if (c + 2 < nc) fill(c + 2, (c + 2) % 3); else CP_COMMIT();
        CP_WAIT(1);

        const int s = c % 3;
        const uint32_t ub = smem_u + (uint32_t)s * STAGE_BYTES;
        const uint32_t uAh = ub, uAl = ub + TILE_BYTES;
        const uint32_t uBh = ub + 2 * TILE_BYTES, uBl = ub + 3 * TILE_BYTES;

        #pragma unroll
        for (int kk = 0; kk < 2; kk++) {
            const int kc = kk * 16;
            uint32_t ah[4][4], al[4][4], bh[2][4], bl[2][4];
            #pragma unroll
            for (int mt = 0; mt < 4; mt++) {
                const uint32_t off = (uint32_t)(((wm * 64 + mt * 16 + lr) * PITCH + kc + lcq) * 2);
                LDSM_X4(ah[mt], uAh + off);
                LDSM_X4(al[mt], uAl + off);
            }
            #pragma unroll
            for (int p = 0; p < 2; p++) {
                const uint32_t off = (uint32_t)(((wn * 32 + p * 16 + lr) * PITCH + kc + lcq) * 2);
                LDSM_X4(bh[p], uBh + off);
                LDSM_X4(bl[p], uBl + off);
            }
            uint32_t bH[4][2] = {{bh[0][0], bh[0][2]}, {bh[0][1], bh[0][3]},
                                 {bh[1][0], bh[1][2]}, {bh[1][1], bh[1][3]}};
            uint32_t bL[4][2] = {{bl[0][0], bl[0][2]}, {bl[0][1], bl[0][3]},
                                 {bl[1][0], bl[1][2]}, {bl[1][1], bl[1][3]}};
            #pragma unroll
            for (int mt = 0; mt < 4; mt++)
                #pragma unroll
                for (int nt = 0; nt < 4; nt++)
                    mma_bf16(acc[mt][nt], ah[mt], bH[nt]);
            #pragma unroll
            for (int mt = 0; mt < 4; mt++)
                #pragma unroll
                for (int nt = 0; nt < 4; nt++)
                    mma_bf16(acc[mt][nt], ah[mt], bL[nt]);
            #pragma unroll
            for (int mt = 0; mt < 4; mt++)
                #pragma unroll
                for (int nt = 0; nt < 4; nt++)
                    mma_bf16(acc[mt][nt], al[mt], bH[nt]);
        }
    }

    // epilogue
    const bool isxi = (mode == 2) && (colBase < DI);
    const bool isz  = (mode == 2) && (colBase >= DI);
    #pragma unroll
    for (int mt = 0; mt < 4; mt++) {
        const int r0 = rowBase + wm * 64 + mt * 16 + g;
        #pragma unroll
        for (int nt = 0; nt < 4; nt++) {
            const int col = wn * 32 + nt * 8 + tq * 2;
            float v0 = acc[mt][nt][0] + bias_s[col];
            float v1 = acc[mt][nt][1] + bias_s[col + 1];
            float v2 = acc[mt][nt][2] + bias_s[col];
            float v3 = acc[mt][nt][3] + bias_s[col + 1];
            if (mode == 1) {
                const float f0 = fcol_s[col], f1 = fcol_s[col + 1];
                v0 = __expf(f0 * __frcp_rn(1.0f + __expf(-v0)));
                v1 = __expf(f1 * __frcp_rn(1.0f + __expf(-v1)));
                v2 = __expf(f0 * __frcp_rn(1.0f + __expf(-v2)));
                v3 = __expf(f1 * __frcp_rn(1.0f + __expf(-v3)));
            }
            if (isz) {
                const int cc = colBase - DI + col;
                float s0 = v0 * __frcp_rn(1.0f + __expf(-v0));
                float s1 = v1 * __frcp_rn(1.0f + __expf(-v1));
                float s2 = v2 * __frcp_rn(1.0f + __expf(-v2));
                float s3 = v3 * __frcp_rn(1.0f + __expf(-v3));
                *(float2*)(Csz + (size_t)r0 * DI + cc)       = make_float2(s0, s1);
                *(float2*)(Csz + (size_t)(r0 + 8) * DI + cc) = make_float2(s2, s3);
            } else {
                const int cc = colBase + col;
                *(float2*)(C0 + (size_t)r0 * ldc + cc)       = make_float2(v0, v1);
                *(float2*)(C0 + (size_t)(r0 + 8) * ldc + cc) = make_float2(v2, v3);
                if (isxi) {
                    uint32_t h0, l0, h1, l1;
                    split2(v0, v1, h0, l0);
                    split2(v2, v3, h1, l1);
                    *(uint32_t*)(Chi + (size_t)r0 * DI + cc)       = h0;
                    *(uint32_t*)(Clo + (size_t)r0 * DI + cc)       = l0;
                    *(uint32_t*)(Chi + (size_t)(r0 + 8) * DI + cc) = h1;
                    *(uint32_t*)(Clo + (size_t)(r0 + 8) * DI + cc) = l1;
                }
            }
        }
    }
}

// ---------------- 2/(v.v) per row ------------------------------------------------
__global__ __launch_bounds__(256) void vv_kernel(const float* __restrict__ v,
                                                 float* __restrict__ sv2)
{
    __shared__ float sm[8];
    const int row = blockIdx.x, tid = threadIdx.x;
    const float4* vr = (const float4*)(v + (size_t)row * DI);
    float s = 0.f;
    #pragma unroll
    for (int i = 0; i < 2; i++) {
        float4 a = vr[tid + i * 256];
        s += a.x * a.x + a.y * a.y + a.z * a.z + a.w * a.w;
    }
    #pragma unroll
    for (int o = 16; o; o >>= 1) s += __shfl_xor_sync(0xffffffffu, s, o);
    if ((tid & 31) == 0) sm[tid >> 5] = s;
    __syncthreads();
    if (tid == 0) {
        float t = 0.f;
        #pragma unroll
        for (int w = 0; w < 8; w++) t += sm[w];
        sv2[row] = 2.0f / t;
    }
}

// ---------------- scan: cp.async prefetch ring, 512 thr x 4 ch --------------------
__global__ __launch_bounds__(SCT, 1) void scan_kernel(
    const float* __restrict__ xi, const float* __restrict__ sz,
    const float* __restrict__ lam, const float* __restrict__ v,
    const float* __restrict__ sv2,
    __nv_bfloat16* __restrict__ gh, __nv_bfloat16* __restrict__ gl)
{
    extern __shared__ float sms[];
    float* ring = sms;                       // [SCP][4][DI]  streams: v,lam,xi,sz
    float* svs  = sms + SCP * 4 * DI;        // [DI] (only TT=DI entries used per batch)
    float* part = svs + DI;                  // [2][16]
    const uint32_t ring_u = smem_u32(ring);

    const int b = blockIdx.x;
    const int tid = threadIdx.x;
    const int lane = tid & 31, wrp = tid >> 5;
    const int c0 = tid * 4;

    const float* xib  = xi  + (size_t)b * TT * DI;
    const float* szb  = sz  + (size_t)b * TT * DI;
    const float* lamb = lam + (size_t)b * TT * DI;
    const float* vb   = v   + (size_t)b * TT * DI;
    const float* svb  = sv2 + (size_t)b * TT;
    __nv_bfloat16* ghb = gh + (size_t)b * TT * DI;
    __nv_bfloat16* glb = gl + (size_t)b * TT * DI;

    // preload sv
    #pragma unroll
    for (int i = 0; i < TT / SCT; i++) svs[tid + i * SCT] = svb[tid + i * SCT];

    auto fill = [&](int t) {
        const int s = t % SCP;
        const uint32_t base = ring_u + (uint32_t)(s * 4 * DI) * 4 + (uint32_t)c0 * 4;
        const size_t o = (size_t)t * DI + c0;
        cp16(base + 0 * DI * 4, vb   + o);
        cp16(base + 1 * DI * 4, lamb + o);
        cp16(base + 2 * DI * 4, xib  + o);
        cp16(base + 3 * DI * 4, szb  + o);
        CP_COMMIT();
    };

    // h0 + g0
    float4 h = *(const float4*)(xib + c0);
    {
        float4 s0 = *(const float4*)(szb + c0);
        uint32_t h0, l0, h1, l1;
        split2(s0.x * h.x, s0.y * h.y, h0, l0);
        split2(s0.z * h.z, s0.w * h.w, h1, l1);
        *(uint2*)(ghb + c0) = make_uint2(h0, h1);
        *(uint2*)(glb + c0) = make_uint2(l0, l1);
    }

    // prologue: steps 1..SCP-1
    #pragma unroll
    for (int t = 1; t < SCP; t++) fill(t);
    CP_WAIT(SCP - 2);
    __syncthreads();

    for (int t = 1; t < TT; t++) {
        const int s = t % SCP;
        const float* st_v = ring + (s * 4 + 0) * DI + c0;
        const float4 vt = *(const float4*)(st_v);
        const float4 lt = *(const float4*)(st_v + 1 * DI);
        const float4 xt = *(const float4*)(st_v + 2 * DI);
        const float4 zt = *(const float4*)(st_v + 3 * DI);

        float p = vt.x * h.x + vt.y * h.y + vt.z * h.z + vt.w * h.w;
        #pragma unroll
        for (int o = 16; o; o >>= 1) p += __shfl_xor_sync(0xffffffffu, p, o);
        if (lane == 0) part[((t & 1) << 4) + wrp] = p;

        const int tf = t + SCP - 1;
        if (tf < TT) fill(tf); else CP_COMMIT();
        CP_WAIT(SCP - 2);
        __syncthreads();

        const float* pp = part + ((t & 1) << 4);
        float4 q0 = *(const float4*)(pp);
        float4 q1 = *(const float4*)(pp + 4);
        float4 q2 = *(const float4*)(pp + 8);
        float4 q3 = *(const float4*)(pp + 12);
        float q = ((q0.x + q0.y) + (q0.z + q0.w)) + ((q1.x + q1.y) + (q1.z + q1.w))
                + ((q2.x + q2.y) + (q2.z + q2.w)) + ((q3.x + q3.y) + (q3.z + q3.w));

        const float s2 = q * svs[t];
        h.x = lt.x * (h.x - s2 * vt.x) + (1.0f - lt.x) * xt.x;
        h.y = lt.y * (h.y - s2 * vt.y) + (1.0f - lt.y) * xt.y;
        h.z = lt.z * (h.z - s2 * vt.z) + (1.0f - lt.z) * xt.z;
        h.w = lt.w * (h.w - s2 * vt.w) + (1.0f - lt.w) * xt.w;

        uint32_t h0, l0, h1, l1;
        split2(zt.x * h.x, zt.y * h.y, h0, l0);
        split2(zt.z * h.z, zt.w * h.w, h1, l1);
        const size_t og = (size_t)t * DI + c0;
        *(uint2*)(ghb + og) = make_uint2(h0, h1);
        *(uint2*)(glb + og) = make_uint2(l0, l1);
    }
}

// ---------------- launcher ----------------------------------------------------------
extern "C" void kernel_launch(void* const* d_in, const int* in_sizes, int n_in,
                              void* d_out, int out_size)
{
    const float* x     = (const float*)d_in[0];
    const float* omega = (const float*)d_in[1];
    const float* Win   = (const float*)d_in[2];
    const float* Wl    = (const float*)d_in[3];
    const float* bl    = (const float*)d_in[4];
    const float* Wv    = (const float*)d_in[5];
    const float* bv    = (const float*)d_in[6];
    const float* Wout  = (const float*)d_in[7];
    float* out = (float*)d_out;

    __nv_bfloat16 *xh, *xl, *winh, *winl, *wlh, *wll, *wvh, *wvl, *woh, *wol;
    __nv_bfloat16 *xih, *xil, *gh, *gl;
    float *xi, *szp, *lam, *v, *sv2, *fcol;
    cudaGetSymbolAddress((void**)&xh,   g_xh);   cudaGetSymbolAddress((void**)&xl,   g_xl);
    cudaGetSymbolAddress((void**)&winh, g_winh); cudaGetSymbolAddress((void**)&winl, g_winl);
    cudaGetSymbolAddress((void**)&wlh,  g_wlh);  cudaGetSymbolAddress((void**)&wll,  g_wll);
    cudaGetSymbolAddress((void**)&wvh,  g_wvh);  cudaGetSymbolAddress((void**)&wvl,  g_wvl);
    cudaGetSymbolAddress((void**)&woh,  g_woh);  cudaGetSymbolAddress((void**)&wol,  g_wol);
    cudaGetSymbolAddress((void**)&xi,   g_xi);
    cudaGetSymbolAddress((void**)&xih,  g_xih);  cudaGetSymbolAddress((void**)&xil,  g_xil);
    cudaGetSymbolAddress((void**)&szp,  g_sz);
    cudaGetSymbolAddress((void**)&lam,  g_lam);  cudaGetSymbolAddress((void**)&v,    g_v);
    cudaGetSymbolAddress((void**)&gh,   g_gh);   cudaGetSymbolAddress((void**)&gl,   g_gl);
    cudaGetSymbolAddress((void**)&sv2,  g_sv2);  cudaGetSymbolAddress((void**)&fcol, g_fcolA);

    cudaFuncSetAttribute(gemm_ps, cudaFuncAttributeMaxDynamicSharedMemorySize, GEMM_SMEM);
    cudaFuncSetAttribute(scan_kernel, cudaFuncAttributeMaxDynamicSharedMemorySize, SCAN_SMEM);

    // 0-4) pre-split x and weights
    split_kernel<<<(MROWS * DM) / 1024, 256>>>(x,    xh,   xl,   MROWS * DM);
    split_kernel<<<(DX * DM)    / 1024, 256>>>(Win,  winh, winl, DX * DM);
    split_kernel<<<(DI * DI)    / 1024, 256>>>(Wl,   wlh,  wll,  DI * DI);
    split_kernel<<<(DI * DI)    / 1024, 256>>>(Wv,   wvh,  wvl,  DI * DI);
    split_kernel<<<(DM * DI)    / 1024, 256>>>(Wout, woh,  wol,  DM * DI);

    // 5) GEMM1: xz = x @ Win^T  -> xi fp32 + xi split + silu(z)
    gemm_ps<<<dim3(DX / 128, MROWS / 128), 256, GEMM_SMEM>>>(
        xh, xl, DM, winh, winl, DM, DM,
        xi, DI, nullptr, nullptr, xih, xil, szp, 2);

    // 6) fcol
    fcol_kernel<<<DI / 256, 256>>>(omega, fcol);

    // 7) GEMM2: lam
    gemm_ps<<<dim3(DI / 128, MROWS / 128), 256, GEMM_SMEM>>>(
        xih, xil, DI, wlh, wll, DI, DI,
        lam, DI, bl, fcol, nullptr, nullptr, nullptr, 1);

    // 8) GEMM3: v
    gemm_ps<<<dim3(DI / 128, MROWS / 128), 256, GEMM_SMEM>>>(
        xih, xil, DI, wvh, wvl, DI, DI,
        v, DI, bv, nullptr, nullptr, nullptr, nullptr, 0);

    // 9) sv2 = 2/(v.v)
    vv_kernel<<<MROWS, 256>>>(v, sv2);

    // 10) scan -> g split
    scan_kernel<<<BB, SCT, SCAN_SMEM>>>(xi, szp, lam, v, sv2, gh, gl);

    // 11) GEMM4: out = g @ Wout^T
    gemm_ps<<<dim3(DM / 128, MROWS / 128), 256, GEMM_SMEM>>>(
        gh, gl, DI, woh, wol, DI, DI,
        out, DM, nullptr, nullptr, nullptr, nullptr, nullptr, 0);
}